// round 7
// baseline (speedup 1.0000x reference)
#include <cuda_runtime.h>
#include <math.h>

#define T_  4
#define C_  512
#define H_  192
#define W_  192
#define HW_ (H_ * W_)
#define CHW_ ((size_t)C_ * HW_)
#define W4_ (W_ / 4)
#define HQ_ (H_ / 4)

struct TCoef { float ax, bx, cx, ay, by, cy; };
struct TInt  { int kx, ky; float fx, fy; };

__device__ float g_part[C_ * 4];
__device__ TCoef g_tc[T_];
__device__ TInt  g_ti[T_];
__device__ int   g_fast;

// ---------------------------------------------------------------------------
// Kernel 1: GAP, 4 partial blocks per channel (proven ~14.6us @ 65% DRAM)
// ---------------------------------------------------------------------------
__global__ void gap_kernel(const float* __restrict__ F) {
    int c = blockIdx.x >> 2;
    int q = blockIdx.x & 3;
    const int n4q = HW_ / 16;
    const float4* p = reinterpret_cast<const float4*>(F + (size_t)c * HW_) + q * n4q;
    float s = 0.f;
    #pragma unroll
    for (int i = 0; i < 9; ++i) {
        float4 v = p[i * 256 + threadIdx.x];
        s += (v.x + v.y) + (v.z + v.w);
    }
    #pragma unroll
    for (int o = 16; o > 0; o >>= 1) s += __shfl_xor_sync(0xffffffffu, s, o);
    __shared__ float sh[8];
    if ((threadIdx.x & 31) == 0) sh[threadIdx.x >> 5] = s;
    __syncthreads();
    if (threadIdx.x == 0) {
        float t = 0.f;
        #pragma unroll
        for (int i = 0; i < 8; ++i) t += sh[i];
        g_part[c * 4 + q] = t;
    }
}

// ---------------------------------------------------------------------------
// Kernel 2: theta
// ---------------------------------------------------------------------------
__global__ void theta_kernel(const float* __restrict__ w1,
                             const float* __restrict__ b1,
                             const float* __restrict__ a,
                             float* __restrict__ out_tail) {
    int warp = threadIdx.x >> 5;
    int lane = threadIdx.x & 31;

    float s = 0.f;
    for (int k = lane; k < C_; k += 32) {
        float4 pp = *reinterpret_cast<const float4*>(&g_part[4 * k]);
        s += ((pp.x + pp.y) + (pp.z + pp.w)) * w1[warp * C_ + k];
    }
    #pragma unroll
    for (int o = 16; o > 0; o >>= 1) s += __shfl_xor_sync(0xffffffffu, s, o);

    __shared__ float Bs[2 * T_];
    if (lane == 0) Bs[warp] = tanhf(s * (1.0f / (float)HW_) + b1[warp]);
    __syncthreads();

    float a00 = a[0], a01 = a[1], a10 = a[2], a11 = a[3];

    if (threadIdx.x == 0)
        g_fast = (a00 == 1.0f && a01 == 0.0f && a10 == 0.0f && a11 == 1.0f) ? 1 : 0;

    if (threadIdx.x < T_) {
        int t = threadIdx.x;
        float bx = Bs[2 * t + 0];
        float by = Bs[2 * t + 1];
        TCoef tc;
        tc.ax = a00;
        tc.bx = a01 * ((float)W_ / (float)H_);
        tc.cx = 0.5f * (a00 - a00 * (float)W_ + a01 * ((float)W_ / (float)H_)
                        - a01 * (float)W_ + bx * (float)W_ + (float)W_ - 1.0f);
        tc.ay = a10 * ((float)H_ / (float)W_);
        tc.by = a11;
        tc.cy = 0.5f * (a10 * ((float)H_ / (float)W_) - a10 * (float)H_ + a11
                        - a11 * (float)H_ + by * (float)H_ + (float)H_ - 1.0f);
        g_tc[t] = tc;

        TInt ti;
        float kxf = floorf(tc.cx), kyf = floorf(tc.cy);
        ti.kx = (int)kxf;  ti.fx = tc.cx - kxf;
        ti.ky = (int)kyf;  ti.fy = tc.cy - kyf;
        g_ti[t] = ti;
    }

    if (threadIdx.x < T_ * 4) out_tail[threadIdx.x] = a[threadIdx.x & 3];
    if (threadIdx.x < 2 * T_) out_tail[T_ * 4 + threadIdx.x] = Bs[threadIdx.x];
}

// ---------------------------------------------------------------------------
// Kernel 3: bilinear warp, 4 OUTPUT ROWS per thread (streaming row pipeline):
// per t, load 5 source rows to emit 4 output rows (vertical reuse 2.0->1.25x).
// Interior threads: no clamps, no masks. R2 load pattern preserved.
// ---------------------------------------------------------------------------
__global__ void __launch_bounds__(256) sample_kernel(const float* __restrict__ F,
                                                     float* __restrict__ out) {
    int idx = blockIdx.x * 256 + threadIdx.x;
    int w4 = idx % W4_;                  // consecutive within warp
    int t2 = idx / W4_;
    int hq = t2 % HQ_;
    int c  = t2 / HQ_;
    int h0 = hq * 4;
    int w0 = w4 * 4;

    const float* Fc = F + (size_t)c * HW_;
    float* outp = out + (size_t)c * HW_ + (size_t)h0 * W_ + w0;
    const float4 z = make_float4(0.f, 0.f, 0.f, 0.f);

    if (g_fast) {
        #pragma unroll
        for (int t = 0; t < T_; ++t) {
            TInt ti = g_ti[t];
            int yb = h0 + ti.ky;                      // first source row
            int s  = ti.kx & 3;                       // uniform
            int base4 = w4 + ((ti.kx - s) >> 2);      // aligned float4 idx (exact)
            float fy = ti.fy, fx = ti.fx;
            float* po = outp + (size_t)t * CHW_;

            #define MIX_(e0, e1) ((e0) + fx * ((e1) - (e0)))
            #define SELECT_(o_, m0,m1,m2,m3,m4,m5,m6,m7)                                   \
                switch (s) {                                                                \
                    case 0: o_.x=MIX_(m0,m1); o_.y=MIX_(m1,m2); o_.z=MIX_(m2,m3); o_.w=MIX_(m3,m4); break; \
                    case 1: o_.x=MIX_(m1,m2); o_.y=MIX_(m2,m3); o_.z=MIX_(m3,m4); o_.w=MIX_(m4,m5); break; \
                    case 2: o_.x=MIX_(m2,m3); o_.y=MIX_(m3,m4); o_.z=MIX_(m4,m5); o_.w=MIX_(m5,m6); break; \
                    default:o_.x=MIX_(m3,m4); o_.y=MIX_(m4,m5); o_.z=MIX_(m5,m6); o_.w=MIX_(m6,m7); break; \
                }

            if ((unsigned)base4 < (unsigned)(W4_ - 1)) {
                // ---- interior: no clamps, no masks ----
                float4 P0, P1;
                {
                    int y = yb; bool vy = (unsigned)y < (unsigned)H_;
                    const float4* rp = reinterpret_cast<const float4*>(
                        Fc + (size_t)(vy ? y : 0) * W_);
                    P0 = __ldg(&rp[base4]); P1 = __ldg(&rp[base4 + 1]);
                    if (!vy) { P0 = z; P1 = z; }
                }
                #pragma unroll
                for (int j = 0; j < 4; ++j) {
                    int y = yb + j + 1; bool vy = (unsigned)y < (unsigned)H_;
                    const float4* rp = reinterpret_cast<const float4*>(
                        Fc + (size_t)(vy ? y : 0) * W_);
                    float4 Q0 = __ldg(&rp[base4]);
                    float4 Q1 = __ldg(&rp[base4 + 1]);
                    if (!vy) { Q0 = z; Q1 = z; }

                    float m0 = P0.x + fy * (Q0.x - P0.x);
                    float m1 = P0.y + fy * (Q0.y - P0.y);
                    float m2 = P0.z + fy * (Q0.z - P0.z);
                    float m3 = P0.w + fy * (Q0.w - P0.w);
                    float m4 = P1.x + fy * (Q1.x - P1.x);
                    float m5 = P1.y + fy * (Q1.y - P1.y);
                    float m6 = P1.z + fy * (Q1.z - P1.z);
                    float m7 = P1.w + fy * (Q1.w - P1.w);

                    float4 o;
                    SELECT_(o, m0, m1, m2, m3, m4, m5, m6, m7)
                    __stcs(reinterpret_cast<float4*>(po + (size_t)j * W_), o);
                    P0 = Q0; P1 = Q1;
                }
            } else {
                // ---- edge: clamped loads + per-column masks ----
                int b0 = min(max(base4, 0), W4_ - 1);
                int b1 = min(max(base4 + 1, 0), W4_ - 1);
                int xb = 4 * base4;
                float4 P0, P1;
                {
                    int y = yb; bool vy = (unsigned)y < (unsigned)H_;
                    const float4* rp = reinterpret_cast<const float4*>(
                        Fc + (size_t)(vy ? y : 0) * W_);
                    P0 = __ldg(&rp[b0]); P1 = __ldg(&rp[b1]);
                    if (!vy) { P0 = z; P1 = z; }
                }
                #pragma unroll
                for (int j = 0; j < 4; ++j) {
                    int y = yb + j + 1; bool vy = (unsigned)y < (unsigned)H_;
                    const float4* rp = reinterpret_cast<const float4*>(
                        Fc + (size_t)(vy ? y : 0) * W_);
                    float4 Q0 = __ldg(&rp[b0]);
                    float4 Q1 = __ldg(&rp[b1]);
                    if (!vy) { Q0 = z; Q1 = z; }

                    float m0 = P0.x + fy * (Q0.x - P0.x);
                    float m1 = P0.y + fy * (Q0.y - P0.y);
                    float m2 = P0.z + fy * (Q0.z - P0.z);
                    float m3 = P0.w + fy * (Q0.w - P0.w);
                    float m4 = P1.x + fy * (Q1.x - P1.x);
                    float m5 = P1.y + fy * (Q1.y - P1.y);
                    float m6 = P1.z + fy * (Q1.z - P1.z);
                    float m7 = P1.w + fy * (Q1.w - P1.w);

                    if ((unsigned)(xb + 0) >= (unsigned)W_) m0 = 0.f;
                    if ((unsigned)(xb + 1) >= (unsigned)W_) m1 = 0.f;
                    if ((unsigned)(xb + 2) >= (unsigned)W_) m2 = 0.f;
                    if ((unsigned)(xb + 3) >= (unsigned)W_) m3 = 0.f;
                    if ((unsigned)(xb + 4) >= (unsigned)W_) m4 = 0.f;
                    if ((unsigned)(xb + 5) >= (unsigned)W_) m5 = 0.f;
                    if ((unsigned)(xb + 6) >= (unsigned)W_) m6 = 0.f;
                    if ((unsigned)(xb + 7) >= (unsigned)W_) m7 = 0.f;

                    float4 o;
                    SELECT_(o, m0, m1, m2, m3, m4, m5, m6, m7)
                    __stcs(reinterpret_cast<float4*>(po + (size_t)j * W_), o);
                    P0 = Q0; P1 = Q1;
                }
            }
            #undef SELECT_
            #undef MIX_
        }
    } else {
        // General affine fallback: 4 rows of scalar gathers
        #pragma unroll
        for (int t = 0; t < T_; ++t) {
            TCoef tc = g_tc[t];
            float* po = outp + (size_t)t * CHW_;
            for (int j = 0; j < 4; ++j) {
                int h = h0 + j;
                float bases_x = tc.bx * (float)h + tc.cx;
                float bases_y = tc.by * (float)h + tc.cy;
                float4 o;
                float* op = reinterpret_cast<float*>(&o);
                #pragma unroll
                for (int k = 0; k < 4; ++k) {
                    float wf = (float)(w0 + k);
                    float ix = tc.ax * wf + bases_x;
                    float iy = tc.ay * wf + bases_y;
                    float ix0f = floorf(ix), iy0f = floorf(iy);
                    float fx = ix - ix0f,   fy = iy - iy0f;
                    int x0 = (int)ix0f, y0 = (int)iy0f;
                    int x1 = x0 + 1,    y1 = y0 + 1;
                    bool vx0 = (unsigned)x0 < (unsigned)W_;
                    bool vx1 = (unsigned)x1 < (unsigned)W_;
                    bool vy0 = (unsigned)y0 < (unsigned)H_;
                    bool vy1 = (unsigned)y1 < (unsigned)H_;
                    const float* r0 = Fc + (size_t)(vy0 ? y0 : 0) * W_;
                    const float* r1 = Fc + (size_t)(vy1 ? y1 : 0) * W_;
                    float v00 = (vy0 && vx0) ? __ldg(r0 + x0) : 0.f;
                    float v01 = (vy0 && vx1) ? __ldg(r0 + x1) : 0.f;
                    float v10 = (vy1 && vx0) ? __ldg(r1 + x0) : 0.f;
                    float v11 = (vy1 && vx1) ? __ldg(r1 + x1) : 0.f;
                    float wx0 = 1.f - fx, wx1 = fx;
                    float wy0 = 1.f - fy, wy1 = fy;
                    op[k] = wy0 * (wx0 * v00 + wx1 * v01) + wy1 * (wx0 * v10 + wx1 * v11);
                }
                __stcs(reinterpret_cast<float4*>(po + (size_t)j * W_), o);
            }
        }
    }
}

// ---------------------------------------------------------------------------
extern "C" void kernel_launch(void* const* d_in, const int* in_sizes, int n_in,
                              void* d_out, int out_size) {
    const float* F  = (const float*)d_in[0];
    const float* w1 = (const float*)d_in[1];
    const float* b1 = (const float*)d_in[2];
    const float* a  = (const float*)d_in[3];
    float* out = (float*)d_out;

    float* out_tail = out + (size_t)T_ * CHW_;

    gap_kernel<<<C_ * 4, 256>>>(F);
    theta_kernel<<<1, 256>>>(w1, b1, a, out_tail);

    const int total = C_ * HQ_ * W4_;    // 1,179,648 threads
    sample_kernel<<<total / 256, 256>>>(F, out);
}